// round 12
// baseline (speedup 1.0000x reference)
#include <cuda_runtime.h>
#include <cuda_bf16.h>
#include <math.h>
#include <stdint.h>

#define TPB   256
#define MT    128
#define DIN   512
#define HH    50
#define DOUT  128
#define MAXN  0.996f
#define MINN  1e-15f

typedef unsigned long long ull;
typedef uint32_t u32;

// ---- smem byte offsets ----
// [0, 36864): W1 staging double buffer (16KB used of each 18KB stage) during GEMM1;
//             U (bf16 hi/lo) aliases it after GEMM1.
#define OFF_UH    0
#define OFF_UL    18432
#define OFF_W3H   36864      // W3 hi 128x144 (resident)
#define OFF_W3L   55296
#define OFF_RED   73728      // 512 f32 exchange buffer
#define OFF_HB1   75776      // 64 f32
#define OFF_HB3   76032      // 128 f32
#define OFF_X2S   76544      // 128 f32
#define OFF_UNS   77056      // 128 f32
#define SMEM_BYTES 77568

__device__ float g_hb1[64];
__device__ float g_hb3[128];
__device__ float g_hb1sq, g_hb3sq;
// W1 pre-rounded to tf32 and packed in m16n8k8 B-fragment order:
// chunk kc (64 k) = 4096 u32; within chunk:
//   off = k16*1024 + (n>>1)*32 + (n&1)*16 + (k&3)*4 + ((k>>2)&3)
__device__ __align__(16) u32 g_w1f[64 * 512];
__device__ __align__(16) __nv_bfloat16 g_w3h[128 * 64];   // k 50..63 zero
__device__ __align__(16) __nv_bfloat16 g_w3l[128 * 64];

__device__ __forceinline__ float artanh_c(float z) {
    z = fminf(z, 1.0f - 1e-7f);
    return 0.5f * logf((1.0f + z) / (1.0f - z));
}

// ---- MMA / async helpers ----
__device__ __forceinline__ void mma_tf32(float* d, const u32* a, const u32* b) {
    asm("mma.sync.aligned.m16n8k8.row.col.f32.tf32.tf32.f32 "
        "{%0,%1,%2,%3}, {%4,%5,%6,%7}, {%8,%9}, {%0,%1,%2,%3};"
        : "+f"(d[0]), "+f"(d[1]), "+f"(d[2]), "+f"(d[3])
        : "r"(a[0]), "r"(a[1]), "r"(a[2]), "r"(a[3]), "r"(b[0]), "r"(b[1]));
}
__device__ __forceinline__ void mma_bf16(float* d, const u32* a, const u32* b) {
    asm("mma.sync.aligned.m16n8k16.row.col.f32.bf16.bf16.f32 "
        "{%0,%1,%2,%3}, {%4,%5,%6,%7}, {%8,%9}, {%0,%1,%2,%3};"
        : "+f"(d[0]), "+f"(d[1]), "+f"(d[2]), "+f"(d[3])
        : "r"(a[0]), "r"(a[1]), "r"(a[2]), "r"(a[3]), "r"(b[0]), "r"(b[1]));
}
__device__ __forceinline__ void ldsm4(u32* r, u32 addr) {
    asm volatile("ldmatrix.sync.aligned.m8n8.x4.shared.b16 {%0,%1,%2,%3}, [%4];"
        : "=r"(r[0]), "=r"(r[1]), "=r"(r[2]), "=r"(r[3]) : "r"(addr));
}
__device__ __forceinline__ u32 f2tf(float x) {
    u32 r; asm("cvt.rna.tf32.f32 %0, %1;" : "=r"(r) : "f"(x)); return r;
}
// truncation split of two floats -> packed bf16x2 hi (exact prefix) + bf16x2 lo
__device__ __forceinline__ void split2(float a, float b, u32& hi, u32& lo) {
    u32 ua = __float_as_uint(a), ub = __float_as_uint(b);
    u32 h;
    asm("prmt.b32 %0, %1, %2, 0x7632;" : "=r"(h) : "r"(ua), "r"(ub));
    float ha = __uint_as_float(ua & 0xFFFF0000u);
    float hb = __uint_as_float(ub & 0xFFFF0000u);
    float la = a - ha, lb = b - hb;
    u32 l;
    asm("cvt.rn.bf16x2.f32 %0, %1, %2;" : "=r"(l) : "f"(lb), "f"(la));
    hi = h; lo = l;
}
__device__ __forceinline__ void cp_async16(u32 sdst, const void* gsrc) {
    asm volatile("cp.async.ca.shared.global [%0], [%1], 16;" :: "r"(sdst), "l"(gsrc));
}
__device__ __forceinline__ void cp_wait_all() {
    asm volatile("cp.async.commit_group;\n\tcp.async.wait_group 0;" ::: "memory");
}

// merged setup: W1 tf32 fragment-packing + W3 bf16 hi/lo + bias precompute (block 0)
__global__ void setup_kernel(const float* __restrict__ W1, const float* __restrict__ W3,
                             const float* __restrict__ b1, const float* __restrict__ b3) {
    for (int idx = blockIdx.x * blockDim.x + threadIdx.x;
         idx < 64 * 512 + 128 * 64; idx += gridDim.x * blockDim.x) {
        if (idx < 64 * 512) {
            int n = idx >> 9, k = idx & 511;
            float v = (n < HH) ? W1[(size_t)n * DIN + k] : 0.0f;
            int off = (k >> 6) * 4096 + ((k >> 4) & 3) * 1024
                    + (n >> 1) * 32 + (n & 1) * 16 + (k & 3) * 4 + ((k >> 2) & 3);
            g_w1f[off] = f2tf(v);
        } else {
            int i = idx - 64 * 512;
            int k = i & 63;
            float v = (k < HH) ? W3[(size_t)(i >> 6) * HH + k] : 0.0f;
            u32 uh = __float_as_uint(v) & 0xFFFF0000u;
            g_w3h[i] = __ushort_as_bfloat16((unsigned short)(uh >> 16));
            g_w3l[i] = __float2bfloat16(v - __uint_as_float(uh));
        }
    }
    if (blockIdx.x == 0) {
        __shared__ float s[256];
        int t = threadIdx.x;

        float v1 = (t < HH) ? b1[t] : 0.0f;
        s[t] = v1 * v1;
        __syncthreads();
        for (int o = 128; o > 0; o >>= 1) { if (t < o) s[t] += s[t + o]; __syncthreads(); }
        float nb2 = s[0];
        __syncthreads();
        {
            float nb = fmaxf(sqrtf(nb2), MINN);
            float th = tanhf(nb);
            float sc = th / nb;
            if (th > MAXN) { sc *= MAXN / th; th = MAXN; }
            if (t < HH) g_hb1[t] = sc * v1;
            if (t == 0) g_hb1sq = th * th;
        }

        float v3 = (t < DOUT) ? b3[t] : 0.0f;
        s[t] = v3 * v3;
        __syncthreads();
        for (int o = 128; o > 0; o >>= 1) { if (t < o) s[t] += s[t + o]; __syncthreads(); }
        nb2 = s[0];
        __syncthreads();
        {
            float nb = fmaxf(sqrtf(nb2), MINN);
            float th = tanhf(nb);
            float sc = th / nb;
            if (th > MAXN) { sc *= MAXN / th; th = MAXN; }
            if (t < DOUT) g_hb3[t] = sc * v3;
            if (t == 0) g_hb3sq = th * th;
        }
    }
}

extern __shared__ __align__(1024) char smraw[];

__global__ __launch_bounds__(TPB, 2)
void hnn_kernel(const float* __restrict__ X, float* __restrict__ out, int N, int nTiles)
{
    const u32 sb = (u32)__cvta_generic_to_shared(smraw);
    float* hb1s = (float*)(smraw + OFF_HB1);
    float* hb3s = (float*)(smraw + OFF_HB3);
    float* red  = (float*)(smraw + OFF_RED);
    float* x2s  = (float*)(smraw + OFF_X2S);
    float* un_s = (float*)(smraw + OFF_UNS);

    const int tid = threadIdx.x;
    const int lane = tid & 31;
    const int c = tid >> 5;
    const int mg = c & 3;             // GEMM1 row group (32 rows)
    const int ng = c >> 2;            // GEMM1 col group
    const int rq = lane >> 2;         // row within fragment octet
    const int cq = lane & 3;          // k-quad within fragment

    // W3 resident (staged once) + biases
    for (int i = tid; i < 1024; i += TPB) {
        int n = i >> 3, j = i & 7;
        cp_async16(sb + OFF_W3H + (u32)(n * 144 + j * 16), g_w3h + n * 64 + j * 8);
        cp_async16(sb + OFF_W3L + (u32)(n * 144 + j * 16), g_w3l + n * 64 + j * 8);
    }
    for (int i = tid; i < 64; i += TPB) hb1s[i] = (i < HH) ? g_hb1[i] : 0.0f;
    if (tid < DOUT) hb3s[tid] = g_hb3[tid];
    const float hb1sq = g_hb1sq;
    const float hb3sq = g_hb3sq;

    // GEMM1 B (W1, tf32 packed) lane base within a chunk stage:
    //   n = ng*32 + nt*8 + rq  ->  pair = ng*16 + nt*4 + (rq>>1), odd = rq&1
    const u32 bColBase = (u32)((ng * 16 + (rq >> 1)) * 128 + (rq & 1) * 64 + cq * 16);
    // GEMM2 lane components
    const u32 a2H = sb + OFF_UH + (u32)((c * 16 + (lane & 15)) * 144 + (lane >> 4) * 16);
    const u32 a2L = a2H + 18432u;
    const u32 b2H = sb + OFF_W3H + (u32)((((lane >> 4) * 8) + (lane & 7)) * 144 + ((lane >> 3) & 1) * 16);
    const u32 b2L = b2H + 18432u;

    // W1 cp.async addressing (flat 16KB chunk copy)
    u32 w1_rel[4];
    const char* w1_gsrc[4];
#pragma unroll
    for (int p = 0; p < 4; p++) {
        int u = tid + 256 * p;              // 0..1023 16B units
        w1_rel[p] = (u32)(u * 16);
        w1_gsrc[p] = (const char*)g_w1f + u * 16;
    }

    float hb1v[8];
    bool hb1_loaded = false;

    for (int tile = blockIdx.x; tile < nTiles; tile += gridDim.x) {
        const int baseRow = tile * MT;

        __syncthreads();   // prior tile's GEMM2 reads (U alias of W1 bufs) complete

        if (!hb1_loaded) {
#pragma unroll
            for (int nt = 0; nt < 4; nt++) {
                float2 hv = *(float2*)(hb1s + ng * 32 + nt * 8 + cq * 2);
                hb1v[nt * 2] = hv.x; hb1v[nt * 2 + 1] = hv.y;
            }
            hb1_loaded = true;
        }

        // A-operand row pointers: rows mg*32 + rq + {0,8,16,24}; k offset = cq
        const float* prow[4];
#pragma unroll
        for (int j = 0; j < 4; j++) {
            int gr = baseRow + mg * 32 + j * 8 + rq;
            int grc = (gr < N) ? gr : (N - 1);
            prow[j] = X + (size_t)grc * DIN + cq;
        }

        float acc[2][4][4];
#pragma unroll
        for (int mt = 0; mt < 2; mt++)
#pragma unroll
            for (int nt = 0; nt < 4; nt++)
#pragma unroll
                for (int e = 0; e < 4; e++) acc[mt][nt][e] = 0.0f;
        float x2a[2] = {0.f, 0.f};
        const int jb = ng * 2;   // x^2 slots owned by this warp

        // prologue: stage W1 chunk 0 -> buf0; preload x values for k16 step 0
#pragma unroll
        for (int p = 0; p < 4; p++)
            cp_async16(sb + w1_rel[p], w1_gsrc[p]);
        float va[4][4];
#pragma unroll
        for (int j = 0; j < 4; j++)
#pragma unroll
            for (int t = 0; t < 4; t++)
                va[j][t] = prow[j][t * 4];
        cp_wait_all();
        __syncthreads();

        // -------- GEMM1: x @ W1^T (TF32 MMA, A direct from global, reg prefetch) --------
        for (int kc = 0; kc < 8; kc++) {
            const u32 stageOff = (u32)((kc & 1) ? 18432u : 0u);
            if (kc < 7) {
                const u32 nW = sb + ((kc & 1) ? 0u : 18432u);
#pragma unroll
                for (int p = 0; p < 4; p++)
                    cp_async16(nW + w1_rel[p], w1_gsrc[p] + (kc + 1) * 16384);
            }

#pragma unroll
            for (int k16 = 0; k16 < 4; k16++) {
                // prefetch next step's x values
                float vn[4][4];
                const bool last = (kc == 7) && (k16 == 3);
                if (!last) {
                    const int noff = (k16 < 3) ? (kc * 64 + (k16 + 1) * 16)
                                               : ((kc + 1) * 64);
#pragma unroll
                    for (int j = 0; j < 4; j++)
#pragma unroll
                        for (int t = 0; t < 4; t++)
                            vn[j][t] = prow[j][noff + t * 4];
                }

                // x^2 partial (this warp's half of the row slots)
#pragma unroll
                for (int h = 0; h < 2; h++)
#pragma unroll
                    for (int t = 0; t < 4; t++)
                        x2a[h] = fmaf(va[jb + h][t], va[jb + h][t], x2a[h]);

                // B fragments: one LDS.128 per n-tile (pre-packed tf32)
                u32 wb[4][4];
#pragma unroll
                for (int nt = 0; nt < 4; nt++) {
                    uint4 w = *(uint4*)(smraw + stageOff + k16 * 4096 + bColBase + nt * 512);
                    wb[nt][0] = w.x; wb[nt][1] = w.y; wb[nt][2] = w.z; wb[nt][3] = w.w;
                }
                // A fragments (tf32 cvt): A[mt][s][4]
                u32 A[2][2][4];
#pragma unroll
                for (int mt = 0; mt < 2; mt++)
#pragma unroll
                    for (int s = 0; s < 2; s++) {
                        A[mt][s][0] = f2tf(va[2 * mt][2 * s]);
                        A[mt][s][1] = f2tf(va[2 * mt + 1][2 * s]);
                        A[mt][s][2] = f2tf(va[2 * mt][2 * s + 1]);
                        A[mt][s][3] = f2tf(va[2 * mt + 1][2 * s + 1]);
                    }
#pragma unroll
                for (int mt = 0; mt < 2; mt++)
#pragma unroll
                    for (int nt = 0; nt < 4; nt++) {
                        mma_tf32(acc[mt][nt], A[mt][0], &wb[nt][0]);
                        mma_tf32(acc[mt][nt], A[mt][1], &wb[nt][2]);
                    }

                if (!last) {
#pragma unroll
                    for (int j = 0; j < 4; j++)
#pragma unroll
                        for (int t = 0; t < 4; t++)
                            va[j][t] = vn[j][t];
                }
            }
            cp_wait_all();
            __syncthreads();
        }

        // -------- Epilogue 1, fully in fragments --------
        float S0[4], S1[4];
#pragma unroll
        for (int mt = 0; mt < 2; mt++)
#pragma unroll
            for (int h = 0; h < 2; h++) {
                int s = mt * 2 + h;
                float a0 = 0.f, a1 = 0.f;
#pragma unroll
                for (int nt = 0; nt < 4; nt++) {
                    float v0 = acc[mt][nt][2 * h], v1 = acc[mt][nt][2 * h + 1];
                    a0 = fmaf(v0, v0, fmaf(v1, v1, a0));
                    a1 = fmaf(v0, hb1v[2 * nt], fmaf(v1, hb1v[2 * nt + 1], a1));
                }
                S0[s] = a0; S1[s] = a1;
            }
#pragma unroll
        for (int s = 0; s < 4; s++) {
            S0[s] += __shfl_xor_sync(~0u, S0[s], 1);
            S0[s] += __shfl_xor_sync(~0u, S0[s], 2);
            S1[s] += __shfl_xor_sync(~0u, S1[s], 1);
            S1[s] += __shfl_xor_sync(~0u, S1[s], 2);
        }
        // x^2 quad-reduce (each warp owns its jb slots)
#pragma unroll
        for (int h = 0; h < 2; h++) {
            float s2 = x2a[h];
            s2 += __shfl_xor_sync(0xffffffffu, s2, 1);
            s2 += __shfl_xor_sync(0xffffffffu, s2, 2);
            if (cq == 0) x2s[mg * 32 + (jb + h) * 8 + rq] = s2;
        }
        if (cq == 0) {
#pragma unroll
            for (int s = 0; s < 4; s++) {
                int row = mg * 32 + (s >> 1) * 16 + (s & 1) * 8 + rq;
                red[ng * 256 + row] = S0[s];
                red[ng * 256 + 128 + row] = S1[s];
            }
        }
        __syncthreads();
        float S0r[4], S1r[4], sx2v[4];
#pragma unroll
        for (int s = 0; s < 4; s++) {
            int row = mg * 32 + (s >> 1) * 16 + (s & 1) * 8 + rq;
            S0r[s] = red[row] + red[256 + row];
            S1r[s] = red[128 + row] + red[384 + row];
            sx2v[s] = x2s[row];
        }
        __syncthreads();

        float C1a[4], C2c[4];
#pragma unroll
        for (int s = 0; s < 4; s++) {
            float nx = fmaxf(sqrtf(sx2v[s]), MINN);
            float th = tanhf(nx);
            float al = th / nx;
            float xn1 = fmaxf(th, MINN);
            float p0 = al * al * S0r[s];
            float p1 = al * S1r[s];
            float mxn = fmaxf(sqrtf(p0), MINN);
            float art = artanh_c(xn1);
            float t = tanhf(mxn / xn1 * art);
            float g = t / mxn;
            float rn = t;
            if (rn > MAXN) { g *= MAXN / rn; rn = MAXN; }
            float xy = g * p1;
            float x2 = rn * rn;
            float den = fmaxf(1.0f + 2.0f * xy + x2 * hb1sq, MINN);
            float A = (1.0f + 2.0f * xy + hb1sq) / den;
            float B = (1.0f - x2) / den;
            float nv2 = A * A * x2 + 2.0f * A * B * xy + B * B * hb1sq;
            float nv = sqrtf(nv2);
            float pf = (nv > MAXN) ? (MAXN / nv) : 1.0f;
            nv = fminf(nv, MAXN);
            float beta = artanh_c(nv) / fmaxf(nv, MINN);
            C1a[s] = beta * pf * A * g * al;
            C2c[s] = beta * pf * B;
        }

        float Q[4] = {0.f, 0.f, 0.f, 0.f};
#pragma unroll
        for (int mt = 0; mt < 2; mt++)
#pragma unroll
            for (int nt = 0; nt < 4; nt++)
#pragma unroll
                for (int h = 0; h < 2; h++) {
                    int s = mt * 2 + h;
                    float xt0 = C1a[s] * acc[mt][nt][2 * h]     + C2c[s] * hb1v[2 * nt];
                    float xt1 = C1a[s] * acc[mt][nt][2 * h + 1] + C2c[s] * hb1v[2 * nt + 1];
                    xt0 = (xt0 > 0.0f) ? xt0 : 0.01f * xt0;
                    xt1 = (xt1 > 0.0f) ? xt1 : 0.01f * xt1;
                    acc[mt][nt][2 * h] = xt0;
                    acc[mt][nt][2 * h + 1] = xt1;
                    Q[s] = fmaf(xt0, xt0, fmaf(xt1, xt1, Q[s]));
                }
#pragma unroll
        for (int s = 0; s < 4; s++) {
            Q[s] += __shfl_xor_sync(~0u, Q[s], 1);
            Q[s] += __shfl_xor_sync(~0u, Q[s], 2);
        }
        if (cq == 0) {
#pragma unroll
            for (int s = 0; s < 4; s++) {
                int row = mg * 32 + (s >> 1) * 16 + (s & 1) * 8 + rq;
                red[ng * 128 + row] = Q[s];
            }
        }
        __syncthreads();
        float gam[4];
#pragma unroll
        for (int s = 0; s < 4; s++) {
            int row = mg * 32 + (s >> 1) * 16 + (s & 1) * 8 + rq;
            float q = red[row] + red[128 + row];
            float nxt = fmaxf(sqrtf(q), MINN);
            float t3 = tanhf(nxt);
            float gm = t3 / nxt;
            if (t3 > MAXN) { gm *= MAXN / t3; t3 = MAXN; }
            gam[s] = gm;
            if (ng == 0 && cq == 0) un_s[row] = fmaxf(t3, MINN);
        }

        // write u = gam * xt straight from fragments as bf16 hi/lo (ldmatrix layout)
#pragma unroll
        for (int mt = 0; mt < 2; mt++) {
            int r0 = mg * 32 + mt * 16 + rq;
#pragma unroll
            for (int nt = 0; nt < 4; nt++) {
                u32 coff = (u32)((ng * 32 + nt * 8 + cq * 2) * 2);
                u32 h, l;
                split2(gam[mt * 2] * acc[mt][nt][0], gam[mt * 2] * acc[mt][nt][1], h, l);
                *(u32*)(smraw + OFF_UH + r0 * 144 + coff) = h;
                *(u32*)(smraw + OFF_UL + r0 * 144 + coff) = l;
                split2(gam[mt * 2 + 1] * acc[mt][nt][2], gam[mt * 2 + 1] * acc[mt][nt][3], h, l);
                *(u32*)(smraw + OFF_UH + (r0 + 8) * 144 + coff) = h;
                *(u32*)(smraw + OFF_UL + (r0 + 8) * 144 + coff) = l;
            }
        }
        __syncthreads();

        // -------- GEMM2: u @ W3^T (HMMA bf16, 3-way split; 16 rows/warp) --------
        float acc2[16][4];
#pragma unroll
        for (int nt = 0; nt < 16; nt++)
#pragma unroll
            for (int e = 0; e < 4; e++) acc2[nt][e] = 0.0f;

#pragma unroll
        for (int k16 = 0; k16 < 4; k16++) {
            u32 ah[4], al2[4];
            ldsm4(ah, a2H + (u32)(k16 * 32));
            ldsm4(al2, a2L + (u32)(k16 * 32));
#pragma unroll
            for (int np = 0; np < 8; np++) {
                u32 bh[4], bl[4];
                u32 boff = (u32)(np * 2304 + k16 * 32);
                ldsm4(bh, b2H + boff);
                ldsm4(bl, b2L + boff);
#pragma unroll
                for (int npi = 0; npi < 2; npi++) {
                    mma_bf16(acc2[np * 2 + npi], ah, bh + npi * 2);
                    mma_bf16(acc2[np * 2 + npi], al2, bh + npi * 2);
                    mma_bf16(acc2[np * 2 + npi], ah, bl + npi * 2);
                }
            }
        }

        float p0a = 0.f, p1a = 0.f, p0b = 0.f, p1b = 0.f;
#pragma unroll
        for (int nt = 0; nt < 16; nt++) {
            float2 hv = *(float2*)(hb3s + nt * 8 + cq * 2);
            p0a = fmaf(acc2[nt][0], acc2[nt][0], fmaf(acc2[nt][1], acc2[nt][1], p0a));
            p1a = fmaf(acc2[nt][0], hv.x, fmaf(acc2[nt][1], hv.y, p1a));
            p0b = fmaf(acc2[nt][2], acc2[nt][2], fmaf(acc2[nt][3], acc2[nt][3], p0b));
            p1b = fmaf(acc2[nt][2], hv.x, fmaf(acc2[nt][3], hv.y, p1b));
        }
#pragma unroll
        for (int o = 1; o <= 2; o <<= 1) {
            p0a += __shfl_xor_sync(0xffffffffu, p0a, o);
            p1a += __shfl_xor_sync(0xffffffffu, p1a, o);
            p0b += __shfl_xor_sync(0xffffffffu, p0b, o);
            p1b += __shfl_xor_sync(0xffffffffu, p1b, o);
        }

        const int row1 = c * 16 + rq;
        const int row2 = row1 + 8;
        float cA1, cB1, cA2, cB2;
        {
            float un = un_s[row1];
            float mxn = fmaxf(sqrtf(p0a), MINN);
            float art = artanh_c(un);
            float t = tanhf(mxn / un * art);
            float g = t / mxn;
            float rn = t;
            if (rn > MAXN) { g *= MAXN / rn; rn = MAXN; }
            float xy = g * p1a;
            float x2 = rn * rn;
            float den = fmaxf(1.0f + 2.0f * xy + x2 * hb3sq, MINN);
            float A = (1.0f + 2.0f * xy + hb3sq) / den;
            float B = (1.0f - x2) / den;
            float nv = sqrtf(A * A * x2 + 2.0f * A * B * xy + B * B * hb3sq);
            float pf = (nv > MAXN) ? (MAXN / nv) : 1.0f;
            cA1 = pf * A * g; cB1 = pf * B;
        }
        {
            float un = un_s[row2];
            float mxn = fmaxf(sqrtf(p0b), MINN);
            float art = artanh_c(un);
            float t = tanhf(mxn / un * art);
            float g = t / mxn;
            float rn = t;
            if (rn > MAXN) { g *= MAXN / rn; rn = MAXN; }
            float xy = g * p1b;
            float x2 = rn * rn;
            float den = fmaxf(1.0f + 2.0f * xy + x2 * hb3sq, MINN);
            float A = (1.0f + 2.0f * xy + hb3sq) / den;
            float B = (1.0f - x2) / den;
            float nv = sqrtf(A * A * x2 + 2.0f * A * B * xy + B * B * hb3sq);
            float pf = (nv > MAXN) ? (MAXN / nv) : 1.0f;
            cA2 = pf * A * g; cB2 = pf * B;
        }

        {
            int g1r = baseRow + row1;
            int g2r = baseRow + row2;
            if (g1r < N) {
                float* o1 = out + (size_t)g1r * DOUT + cq * 2;
#pragma unroll
                for (int nt = 0; nt < 16; nt++) {
                    float2 hv = *(float2*)(hb3s + nt * 8 + cq * 2);
                    float2 vv;
                    vv.x = cA1 * acc2[nt][0] + cB1 * hv.x;
                    vv.y = cA1 * acc2[nt][1] + cB1 * hv.y;
                    *(float2*)(o1 + nt * 8) = vv;
                }
            }
            if (g2r < N) {
                float* o2 = out + (size_t)g2r * DOUT + cq * 2;
#pragma unroll
                for (int nt = 0; nt < 16; nt++) {
                    float2 hv = *(float2*)(hb3s + nt * 8 + cq * 2);
                    float2 vv;
                    vv.x = cA2 * acc2[nt][2] + cB2 * hv.x;
                    vv.y = cA2 * acc2[nt][3] + cB2 * hv.y;
                    *(float2*)(o2 + nt * 8) = vv;
                }
            }
        }
    }
}

extern "C" void kernel_launch(void* const* d_in, const int* in_sizes, int n_in,
                              void* d_out, int out_size) {
    const float* x  = (const float*)d_in[0];
    const float* W1 = (const float*)d_in[1];
    const float* b1 = (const float*)d_in[2];
    const float* W3 = (const float*)d_in[3];
    const float* b3 = (const float*)d_in[4];
    float* out = (float*)d_out;
    int N = in_sizes[0] / DIN;
    int nTiles = (N + MT - 1) / MT;
    int grid = nTiles < 296 ? nTiles : 296;

    cudaFuncSetAttribute(hnn_kernel, cudaFuncAttributeMaxDynamicSharedMemorySize, SMEM_BYTES);

    setup_kernel<<<161, 256>>>(W1, W3, b1, b3);
    hnn_kernel<<<grid, TPB, SMEM_BYTES>>>(x, out, N, nTiles);
}

// round 13
// speedup vs baseline: 1.5452x; 1.5452x over previous
#include <cuda_runtime.h>
#include <cuda_bf16.h>
#include <cuda_fp16.h>
#include <math.h>
#include <stdint.h>

#define TPB   256
#define MT    128
#define DIN   512
#define HH    50
#define DOUT  128
#define MAXN  0.996f
#define MINN  1e-15f

typedef unsigned long long ull;
typedef uint32_t u32;

// ---- smem byte offsets ----
// [0, 36864): W1 fp16 staging double buffer (2 x 9216B) during GEMM1;
//             U (bf16 hi/lo, 2 x 18432B) aliases the region after GEMM1.
#define OFF_UH    0
#define OFF_UL    18432
#define OFF_W3H   36864      // W3 hi 128x144 (resident)
#define OFF_W3L   55296
#define OFF_RED   73728      // 512 f32 exchange buffer
#define OFF_HB1   75776      // 64 f32
#define OFF_HB3   76032      // 128 f32
#define OFF_X2S   76544      // 128 f32
#define OFF_UNS   77056      // 128 f32
#define SMEM_BYTES 77568

__device__ float g_hb1[64];
__device__ float g_hb3[128];
__device__ float g_hb1sq, g_hb3sq;
__device__ __align__(16) __half g_w1f[64 * 512];          // fp16 W1, rows 50..63 zero
__device__ __align__(16) __nv_bfloat16 g_w3h[128 * 64];   // k 50..63 zero
__device__ __align__(16) __nv_bfloat16 g_w3l[128 * 64];

__device__ __forceinline__ float artanh_c(float z) {
    z = fminf(z, 1.0f - 1e-7f);
    return 0.5f * logf((1.0f + z) / (1.0f - z));
}

// ---- MMA / async helpers ----
__device__ __forceinline__ void mma_f16(float* d, const u32* a, const u32* b) {
    asm("mma.sync.aligned.m16n8k16.row.col.f32.f16.f16.f32 "
        "{%0,%1,%2,%3}, {%4,%5,%6,%7}, {%8,%9}, {%0,%1,%2,%3};"
        : "+f"(d[0]), "+f"(d[1]), "+f"(d[2]), "+f"(d[3])
        : "r"(a[0]), "r"(a[1]), "r"(a[2]), "r"(a[3]), "r"(b[0]), "r"(b[1]));
}
__device__ __forceinline__ void mma_bf16(float* d, const u32* a, const u32* b) {
    asm("mma.sync.aligned.m16n8k16.row.col.f32.bf16.bf16.f32 "
        "{%0,%1,%2,%3}, {%4,%5,%6,%7}, {%8,%9}, {%0,%1,%2,%3};"
        : "+f"(d[0]), "+f"(d[1]), "+f"(d[2]), "+f"(d[3])
        : "r"(a[0]), "r"(a[1]), "r"(a[2]), "r"(a[3]), "r"(b[0]), "r"(b[1]));
}
__device__ __forceinline__ void ldsm4(u32* r, u32 addr) {
    asm volatile("ldmatrix.sync.aligned.m8n8.x4.shared.b16 {%0,%1,%2,%3}, [%4];"
        : "=r"(r[0]), "=r"(r[1]), "=r"(r[2]), "=r"(r[3]) : "r"(addr));
}
// pack two f32 -> f16x2 (lo in low half)
__device__ __forceinline__ u32 packf16(float lo, float hi) {
    u32 r; asm("cvt.rn.f16x2.f32 %0, %1, %2;" : "=r"(r) : "f"(hi), "f"(lo)); return r;
}
// truncation split of two floats -> packed bf16x2 hi (exact prefix) + bf16x2 lo
__device__ __forceinline__ void split2(float a, float b, u32& hi, u32& lo) {
    u32 ua = __float_as_uint(a), ub = __float_as_uint(b);
    u32 h;
    asm("prmt.b32 %0, %1, %2, 0x7632;" : "=r"(h) : "r"(ua), "r"(ub));
    float ha = __uint_as_float(ua & 0xFFFF0000u);
    float hb = __uint_as_float(ub & 0xFFFF0000u);
    float la = a - ha, lb = b - hb;
    u32 l;
    asm("cvt.rn.bf16x2.f32 %0, %1, %2;" : "=r"(l) : "f"(lb), "f"(la));
    hi = h; lo = l;
}
__device__ __forceinline__ void cp_async16(u32 sdst, const void* gsrc) {
    asm volatile("cp.async.ca.shared.global [%0], [%1], 16;" :: "r"(sdst), "l"(gsrc));
}
__device__ __forceinline__ void cp_wait_all() {
    asm volatile("cp.async.commit_group;\n\tcp.async.wait_group 0;" ::: "memory");
}

// merged setup: W1 fp16 + W3 bf16 hi/lo + bias precompute (block 0)
__global__ void setup_kernel(const float* __restrict__ W1, const float* __restrict__ W3,
                             const float* __restrict__ b1, const float* __restrict__ b3) {
    for (int idx = blockIdx.x * blockDim.x + threadIdx.x;
         idx < 64 * 512 + 128 * 64; idx += gridDim.x * blockDim.x) {
        if (idx < 64 * 512) {
            int n = idx >> 9;
            float v = (n < HH) ? W1[(size_t)n * DIN + (idx & 511)] : 0.0f;
            g_w1f[idx] = __float2half_rn(v);
        } else {
            int i = idx - 64 * 512;
            int k = i & 63;
            float v = (k < HH) ? W3[(size_t)(i >> 6) * HH + k] : 0.0f;
            u32 uh = __float_as_uint(v) & 0xFFFF0000u;
            g_w3h[i] = __ushort_as_bfloat16((unsigned short)(uh >> 16));
            g_w3l[i] = __float2bfloat16(v - __uint_as_float(uh));
        }
    }
    if (blockIdx.x == 0) {
        __shared__ float s[256];
        int t = threadIdx.x;

        float v1 = (t < HH) ? b1[t] : 0.0f;
        s[t] = v1 * v1;
        __syncthreads();
        for (int o = 128; o > 0; o >>= 1) { if (t < o) s[t] += s[t + o]; __syncthreads(); }
        float nb2 = s[0];
        __syncthreads();
        {
            float nb = fmaxf(sqrtf(nb2), MINN);
            float th = tanhf(nb);
            float sc = th / nb;
            if (th > MAXN) { sc *= MAXN / th; th = MAXN; }
            if (t < HH) g_hb1[t] = sc * v1;
            if (t == 0) g_hb1sq = th * th;
        }

        float v3 = (t < DOUT) ? b3[t] : 0.0f;
        s[t] = v3 * v3;
        __syncthreads();
        for (int o = 128; o > 0; o >>= 1) { if (t < o) s[t] += s[t + o]; __syncthreads(); }
        nb2 = s[0];
        __syncthreads();
        {
            float nb = fmaxf(sqrtf(nb2), MINN);
            float th = tanhf(nb);
            float sc = th / nb;
            if (th > MAXN) { sc *= MAXN / th; th = MAXN; }
            if (t < DOUT) g_hb3[t] = sc * v3;
            if (t == 0) g_hb3sq = th * th;
        }
    }
}

extern __shared__ __align__(1024) char smraw[];

__global__ __launch_bounds__(TPB, 2)
void hnn_kernel(const float* __restrict__ X, float* __restrict__ out, int N, int nTiles)
{
    const u32 sb = (u32)__cvta_generic_to_shared(smraw);
    float* hb1s = (float*)(smraw + OFF_HB1);
    float* hb3s = (float*)(smraw + OFF_HB3);
    float* red  = (float*)(smraw + OFF_RED);
    float* x2s  = (float*)(smraw + OFF_X2S);
    float* un_s = (float*)(smraw + OFF_UNS);

    const int tid = threadIdx.x;
    const int lane = tid & 31;
    const int c = tid >> 5;
    const int mg = c & 3;             // GEMM1 row group (32 rows)
    const int ng = c >> 2;            // GEMM1 col group
    const int rq = lane >> 2;         // row-quad within fragment
    const int cq = lane & 3;          // col-quad within fragment

    // W3 resident (staged once) + biases
    for (int i = tid; i < 1024; i += TPB) {
        int n = i >> 3, j = i & 7;
        cp_async16(sb + OFF_W3H + (u32)(n * 144 + j * 16), g_w3h + n * 64 + j * 8);
        cp_async16(sb + OFF_W3L + (u32)(n * 144 + j * 16), g_w3l + n * 64 + j * 8);
    }
    for (int i = tid; i < 64; i += TPB) hb1s[i] = (i < HH) ? g_hb1[i] : 0.0f;
    if (tid < DOUT) hb3s[tid] = g_hb3[tid];
    const float hb1sq = g_hb1sq;
    const float hb3sq = g_hb3sq;

    // GEMM1 B (W1 fp16) ldmatrix lane components (rows n = bN, 144B stride)
    const u32 bN   = (u32)(ng * 32 + ((lane >> 4) * 8) + (lane & 7));
    const u32 bKof = (u32)(((lane >> 3) & 1) * 16);
    // GEMM2 lane components
    const u32 a2H = sb + OFF_UH + (u32)((c * 16 + (lane & 15)) * 144 + (lane >> 4) * 16);
    const u32 a2L = a2H + 18432u;
    const u32 b2H = sb + OFF_W3H + (u32)((((lane >> 4) * 8) + (lane & 7)) * 144 + ((lane >> 3) & 1) * 16);
    const u32 b2L = b2H + 18432u;

    // W1 cp.async addressing (512 x 16B units per chunk; 2 per thread)
    u32 w1_rel[2];
    const __half* w1_gsrc[2];
#pragma unroll
    for (int p = 0; p < 2; p++) {
        int u = tid + 256 * p;              // 0..511
        int n = u >> 3, j = u & 7;
        w1_rel[p] = (u32)(n * 144 + j * 16);
        w1_gsrc[p] = g_w1f + n * 512 + j * 8;
    }

    float hb1v[8];
    bool hb1_loaded = false;

    for (int tile = blockIdx.x; tile < nTiles; tile += gridDim.x) {
        const int baseRow = tile * MT;

        __syncthreads();   // prior tile's GEMM2 reads (U alias of W1 bufs) complete

        if (!hb1_loaded) {
#pragma unroll
            for (int nt = 0; nt < 4; nt++) {
                float2 hv = *(float2*)(hb1s + ng * 32 + nt * 8 + cq * 2);
                hb1v[nt * 2] = hv.x; hb1v[nt * 2 + 1] = hv.y;
            }
            hb1_loaded = true;
        }

        // A-operand row pointers (fragment-direct): rows mg*32 + rq + {0,8,16,24}
        const float* prow[4];
#pragma unroll
        for (int j = 0; j < 4; j++) {
            int gr = baseRow + mg * 32 + j * 8 + rq;
            int grc = (gr < N) ? gr : (N - 1);
            prow[j] = X + (size_t)grc * DIN + 2 * cq;
        }

        float acc[2][4][4];
#pragma unroll
        for (int mt = 0; mt < 2; mt++)
#pragma unroll
            for (int nt = 0; nt < 4; nt++)
#pragma unroll
                for (int e = 0; e < 4; e++) acc[mt][nt][e] = 0.0f;
        float x2a[4] = {0.f, 0.f, 0.f, 0.f};

        // prologue: stage W1 chunk 0 -> buf0; preload x fragments for k16 step 0
#pragma unroll
        for (int p = 0; p < 2; p++)
            cp_async16(sb + w1_rel[p], w1_gsrc[p]);
        float2 v[8];
#pragma unroll
        for (int j = 0; j < 4; j++) {
            v[2 * j]     = *(const float2*)(prow[j]);
            v[2 * j + 1] = *(const float2*)(prow[j] + 8);
        }
        cp_wait_all();
        __syncthreads();

        // -------- GEMM1: x @ W1^T (single-pass FP16 HMMA, A direct from global,
        //          register-prefetch pipeline on A) --------
        for (int kc = 0; kc < 8; kc++) {
            const u32 bW = sb + ((kc & 1) ? 9216u : 0u);
            if (kc < 7) {
                const u32 nW = sb + ((kc & 1) ? 0u : 9216u);
#pragma unroll
                for (int p = 0; p < 2; p++)
                    cp_async16(nW + w1_rel[p], w1_gsrc[p] + (kc + 1) * 64);
            }

#pragma unroll
            for (int k16 = 0; k16 < 4; k16++) {
                // prefetch next k16 step's fragments
                float2 vn[8];
                const bool last = (kc == 7) && (k16 == 3);
                if (!last) {
                    const int noff = (k16 < 3) ? (kc * 64 + (k16 + 1) * 16)
                                               : ((kc + 1) * 64);
#pragma unroll
                    for (int j = 0; j < 4; j++) {
                        vn[2 * j]     = *(const float2*)(prow[j] + noff);
                        vn[2 * j + 1] = *(const float2*)(prow[j] + noff + 8);
                    }
                }

                if (ng == 0) {
#pragma unroll
                    for (int j = 0; j < 4; j++) {
                        x2a[j] = fmaf(v[2 * j].x, v[2 * j].x, x2a[j]);
                        x2a[j] = fmaf(v[2 * j].y, v[2 * j].y, x2a[j]);
                        x2a[j] = fmaf(v[2 * j + 1].x, v[2 * j + 1].x, x2a[j]);
                        x2a[j] = fmaf(v[2 * j + 1].y, v[2 * j + 1].y, x2a[j]);
                    }
                }
                // A fragments: fp16 single-pass (same layout as bf16 k16)
                u32 ah[2][4];
                ah[0][0] = packf16(v[0].x, v[0].y);
                ah[0][1] = packf16(v[2].x, v[2].y);
                ah[0][2] = packf16(v[1].x, v[1].y);
                ah[0][3] = packf16(v[3].x, v[3].y);
                ah[1][0] = packf16(v[4].x, v[4].y);
                ah[1][1] = packf16(v[6].x, v[6].y);
                ah[1][2] = packf16(v[5].x, v[5].y);
                ah[1][3] = packf16(v[7].x, v[7].y);

                u32 bh[8];
#pragma unroll
                for (int np = 0; np < 2; np++) {
                    u32 boff = (bN + (u32)(np * 16)) * 144u + (u32)(k16 * 32) + bKof;
                    ldsm4(bh + np * 4, bW + boff);
                }
#pragma unroll
                for (int mt = 0; mt < 2; mt++)
#pragma unroll
                    for (int nt = 0; nt < 4; nt++)
                        mma_f16(acc[mt][nt], ah[mt], bh + nt * 2);

                if (!last) {
#pragma unroll
                    for (int j = 0; j < 8; j++) v[j] = vn[j];
                }
            }
            cp_wait_all();
            __syncthreads();
        }

        // -------- Epilogue 1, fully in fragments --------
        float S0[4], S1[4];
#pragma unroll
        for (int mt = 0; mt < 2; mt++)
#pragma unroll
            for (int h = 0; h < 2; h++) {
                int s = mt * 2 + h;
                float a0 = 0.f, a1 = 0.f;
#pragma unroll
                for (int nt = 0; nt < 4; nt++) {
                    float v0 = acc[mt][nt][2 * h], v1 = acc[mt][nt][2 * h + 1];
                    a0 = fmaf(v0, v0, fmaf(v1, v1, a0));
                    a1 = fmaf(v0, hb1v[2 * nt], fmaf(v1, hb1v[2 * nt + 1], a1));
                }
                S0[s] = a0; S1[s] = a1;
            }
#pragma unroll
        for (int s = 0; s < 4; s++) {
            S0[s] += __shfl_xor_sync(~0u, S0[s], 1);
            S0[s] += __shfl_xor_sync(~0u, S0[s], 2);
            S1[s] += __shfl_xor_sync(~0u, S1[s], 1);
            S1[s] += __shfl_xor_sync(~0u, S1[s], 2);
        }
        if (ng == 0) {
#pragma unroll
            for (int h = 0; h < 4; h++) {
                float s2 = x2a[h];
                s2 += __shfl_xor_sync(0xffffffffu, s2, 1);
                s2 += __shfl_xor_sync(0xffffffffu, s2, 2);
                if (cq == 0) x2s[mg * 32 + h * 8 + rq] = s2;
            }
        }
        if (cq == 0) {
#pragma unroll
            for (int s = 0; s < 4; s++) {
                int row = mg * 32 + (s >> 1) * 16 + (s & 1) * 8 + rq;
                red[ng * 256 + row] = S0[s];
                red[ng * 256 + 128 + row] = S1[s];
            }
        }
        __syncthreads();
        float S0r[4], S1r[4], sx2v[4];
#pragma unroll
        for (int s = 0; s < 4; s++) {
            int row = mg * 32 + (s >> 1) * 16 + (s & 1) * 8 + rq;
            S0r[s] = red[row] + red[256 + row];
            S1r[s] = red[128 + row] + red[384 + row];
            sx2v[s] = x2s[row];
        }
        __syncthreads();

        float C1a[4], C2c[4];
#pragma unroll
        for (int s = 0; s < 4; s++) {
            float nx = fmaxf(sqrtf(sx2v[s]), MINN);
            float th = tanhf(nx);
            float al = th / nx;
            float xn1 = fmaxf(th, MINN);
            float p0 = al * al * S0r[s];
            float p1 = al * S1r[s];
            float mxn = fmaxf(sqrtf(p0), MINN);
            float art = artanh_c(xn1);
            float t = tanhf(mxn / xn1 * art);
            float g = t / mxn;
            float rn = t;
            if (rn > MAXN) { g *= MAXN / rn; rn = MAXN; }
            float xy = g * p1;
            float x2 = rn * rn;
            float den = fmaxf(1.0f + 2.0f * xy + x2 * hb1sq, MINN);
            float A = (1.0f + 2.0f * xy + hb1sq) / den;
            float B = (1.0f - x2) / den;
            float nv2 = A * A * x2 + 2.0f * A * B * xy + B * B * hb1sq;
            float nv = sqrtf(nv2);
            float pf = (nv > MAXN) ? (MAXN / nv) : 1.0f;
            nv = fminf(nv, MAXN);
            float beta = artanh_c(nv) / fmaxf(nv, MINN);
            C1a[s] = beta * pf * A * g * al;
            C2c[s] = beta * pf * B;
        }

        float Q[4] = {0.f, 0.f, 0.f, 0.f};
#pragma unroll
        for (int mt = 0; mt < 2; mt++)
#pragma unroll
            for (int nt = 0; nt < 4; nt++)
#pragma unroll
                for (int h = 0; h < 2; h++) {
                    int s = mt * 2 + h;
                    float xt0 = C1a[s] * acc[mt][nt][2 * h]     + C2c[s] * hb1v[2 * nt];
                    float xt1 = C1a[s] * acc[mt][nt][2 * h + 1] + C2c[s] * hb1v[2 * nt + 1];
                    xt0 = (xt0 > 0.0f) ? xt0 : 0.01f * xt0;
                    xt1 = (xt1 > 0.0f) ? xt1 : 0.01f * xt1;
                    acc[mt][nt][2 * h] = xt0;
                    acc[mt][nt][2 * h + 1] = xt1;
                    Q[s] = fmaf(xt0, xt0, fmaf(xt1, xt1, Q[s]));
                }
#pragma unroll
        for (int s = 0; s < 4; s++) {
            Q[s] += __shfl_xor_sync(~0u, Q[s], 1);
            Q[s] += __shfl_xor_sync(~0u, Q[s], 2);
        }
        if (cq == 0) {
#pragma unroll
            for (int s = 0; s < 4; s++) {
                int row = mg * 32 + (s >> 1) * 16 + (s & 1) * 8 + rq;
                red[ng * 128 + row] = Q[s];
            }
        }
        __syncthreads();
        float gam[4];
#pragma unroll
        for (int s = 0; s < 4; s++) {
            int row = mg * 32 + (s >> 1) * 16 + (s & 1) * 8 + rq;
            float q = red[row] + red[128 + row];
            float nxt = fmaxf(sqrtf(q), MINN);
            float t3 = tanhf(nxt);
            float gm = t3 / nxt;
            if (t3 > MAXN) { gm *= MAXN / t3; t3 = MAXN; }
            gam[s] = gm;
            if (ng == 0 && cq == 0) un_s[row] = fmaxf(t3, MINN);
        }

        // write u = gam * xt straight from fragments as bf16 hi/lo (ldmatrix layout)
#pragma unroll
        for (int mt = 0; mt < 2; mt++) {
            int r0 = mg * 32 + mt * 16 + rq;
#pragma unroll
            for (int nt = 0; nt < 4; nt++) {
                u32 coff = (u32)((ng * 32 + nt * 8 + cq * 2) * 2);
                u32 h, l;
                split2(gam[mt * 2] * acc[mt][nt][0], gam[mt * 2] * acc[mt][nt][1], h, l);
                *(u32*)(smraw + OFF_UH + r0 * 144 + coff) = h;
                *(u32*)(smraw + OFF_UL + r0 * 144 + coff) = l;
                split2(gam[mt * 2 + 1] * acc[mt][nt][2], gam[mt * 2 + 1] * acc[mt][nt][3], h, l);
                *(u32*)(smraw + OFF_UH + (r0 + 8) * 144 + coff) = h;
                *(u32*)(smraw + OFF_UL + (r0 + 8) * 144 + coff) = l;
            }
        }
        __syncthreads();

        // -------- GEMM2: u @ W3^T (HMMA bf16, 3-way split; 16 rows/warp) --------
        float acc2[16][4];
#pragma unroll
        for (int nt = 0; nt < 16; nt++)
#pragma unroll
            for (int e = 0; e < 4; e++) acc2[nt][e] = 0.0f;

#pragma unroll
        for (int k16 = 0; k16 < 4; k16++) {
            u32 ah[4], al2[4];
            ldsm4(ah, a2H + (u32)(k16 * 32));
            ldsm4(al2, a2L + (u32)(k16 * 32));
#pragma unroll
            for (int np = 0; np < 8; np++) {
                u32 bh[4], bl[4];
                u32 boff = (u32)(np * 2304 + k16 * 32);
                ldsm4(bh, b2H + boff);
                ldsm4(bl, b2L + boff);
#pragma unroll
                for (int npi = 0; npi < 2; npi++) {
                    mma_bf16(acc2[np * 2 + npi], ah, bh + npi * 2);
                    mma_bf16(acc2[np * 2 + npi], al2, bh + npi * 2);
                    mma_bf16(acc2[np * 2 + npi], ah, bl + npi * 2);
                }
            }
        }

        float p0a = 0.f, p1a = 0.f, p0b = 0.f, p1b = 0.f;
#pragma unroll
        for (int nt = 0; nt < 16; nt++) {
            float2 hv = *(float2*)(hb3s + nt * 8 + cq * 2);
            p0a = fmaf(acc2[nt][0], acc2[nt][0], fmaf(acc2[nt][1], acc2[nt][1], p0a));
            p1a = fmaf(acc2[nt][0], hv.x, fmaf(acc2[nt][1], hv.y, p1a));
            p0b = fmaf(acc2[nt][2], acc2[nt][2], fmaf(acc2[nt][3], acc2[nt][3], p0b));
            p1b = fmaf(acc2[nt][2], hv.x, fmaf(acc2[nt][3], hv.y, p1b));
        }
#pragma unroll
        for (int o = 1; o <= 2; o <<= 1) {
            p0a += __shfl_xor_sync(0xffffffffu, p0a, o);
            p1a += __shfl_xor_sync(0xffffffffu, p1a, o);
            p0b += __shfl_xor_sync(0xffffffffu, p0b, o);
            p1b += __shfl_xor_sync(0xffffffffu, p1b, o);
        }

        const int row1 = c * 16 + rq;
        const int row2 = row1 + 8;
        float cA1, cB1, cA2, cB2;
        {
            float un = un_s[row1];
            float mxn = fmaxf(sqrtf(p0a), MINN);
            float art = artanh_c(un);
            float t = tanhf(mxn / un * art);
            float g = t / mxn;
            float rn = t;
            if (rn > MAXN) { g *= MAXN / rn; rn = MAXN; }
            float xy = g * p1a;
            float x2 = rn * rn;
            float den = fmaxf(1.0f + 2.0f * xy + x2 * hb3sq, MINN);
            float A = (1.0f + 2.0f * xy + hb3sq) / den;
            float B = (1.0f - x2) / den;
            float nv = sqrtf(A * A * x2 + 2.0f * A * B * xy + B * B * hb3sq);
            float pf = (nv > MAXN) ? (MAXN / nv) : 1.0f;
            cA1 = pf * A * g; cB1 = pf * B;
        }
        {
            float un = un_s[row2];
            float mxn = fmaxf(sqrtf(p0b), MINN);
            float art = artanh_c(un);
            float t = tanhf(mxn / un * art);
            float g = t / mxn;
            float rn = t;
            if (rn > MAXN) { g *= MAXN / rn; rn = MAXN; }
            float xy = g * p1b;
            float x2 = rn * rn;
            float den = fmaxf(1.0f + 2.0f * xy + x2 * hb3sq, MINN);
            float A = (1.0f + 2.0f * xy + hb3sq) / den;
            float B = (1.0f - x2) / den;
            float nv = sqrtf(A * A * x2 + 2.0f * A * B * xy + B * B * hb3sq);
            float pf = (nv > MAXN) ? (MAXN / nv) : 1.0f;
            cA2 = pf * A * g; cB2 = pf * B;
        }

        {
            int g1r = baseRow + row1;
            int g2r = baseRow + row2;
            if (g1r < N) {
                float* o1 = out + (size_t)g1r * DOUT + cq * 2;
#pragma unroll
                for (int nt = 0; nt < 16; nt++) {
                    float2 hv = *(float2*)(hb3s + nt * 8 + cq * 2);
                    float2 vv;
                    vv.x = cA1 * acc2[nt][0] + cB1 * hv.x;
                    vv.y = cA1 * acc2[nt][1] + cB1 * hv.y;
                    *(float2*)(o1 + nt * 8) = vv;
                }
            }
            if (g2r < N) {
                float* o2 = out + (size_t)g2r * DOUT + cq * 2;
#pragma unroll
                for (int nt = 0; nt < 16; nt++) {
                    float2 hv = *(float2*)(hb3s + nt * 8 + cq * 2);
                    float2 vv;
                    vv.x = cA2 * acc2[nt][2] + cB2 * hv.x;
                    vv.y = cA2 * acc2[nt][3] + cB2 * hv.y;
                    *(float2*)(o2 + nt * 8) = vv;
                }
            }
        }
    }
}

extern "C" void kernel_launch(void* const* d_in, const int* in_sizes, int n_in,
                              void* d_out, int out_size) {
    const float* x  = (const float*)d_in[0];
    const float* W1 = (const float*)d_in[1];
    const float* b1 = (const float*)d_in[2];
    const float* W3 = (const float*)d_in[3];
    const float* b3 = (const float*)d_in[4];
    float* out = (float*)d_out;
    int N = in_sizes[0] / DIN;
    int nTiles = (N + MT - 1) / MT;
    int grid = nTiles < 296 ? nTiles : 296;

    cudaFuncSetAttribute(hnn_kernel, cudaFuncAttributeMaxDynamicSharedMemorySize, SMEM_BYTES);

    setup_kernel<<<161, 256>>>(W1, W3, b1, b3);
    hnn_kernel<<<grid, TPB, SMEM_BYTES>>>(x, out, N, nTiles);
}